// round 1
// baseline (speedup 1.0000x reference)
#include <cuda_runtime.h>
#include <math.h>

#define Bx 2
#define Tx 2048
#define Hx 2560
#define NHx 8
#define NKVx 4
#define Dx 256
#define WINDOWx 1024
#define NTOK (Bx*Tx)      /* 4096 */
#define QSTR (NHx*Dx)     /* 2048 */
#define KSTR (NKVx*Dx)    /* 1024 */

// ---------------- scratch (device globals; no allocation allowed) -----------
__device__ float g_q[NTOK*QSTR];     // 32 MB
__device__ float g_k[NTOK*KSTR];     // 16 MB
__device__ float g_v[NTOK*KSTR];     // 16 MB
__device__ float g_att[NTOK*QSTR];   // 32 MB
__device__ float g_pos[NTOK];

// ---------------- position kernel ------------------------------------------
__global__ void pos_kernel(const int* __restrict__ seg, const int* __restrict__ cur,
                           float* __restrict__ pos)
{
    const int b = blockIdx.x;
    const int tid = threadIdx.x;
    const int* row = seg + b*Tx;
    __shared__ int sv[256], si[256];
    int bestv = -2147483647, besti = 0;
    for (int t = tid; t < Tx; t += 256) {
        int v = row[t];
        if (v > bestv) { bestv = v; besti = t; }
    }
    sv[tid] = bestv; si[tid] = besti;
    __syncthreads();
    for (int s = 128; s > 0; s >>= 1) {
        if (tid < s) {
            int v2 = sv[tid+s], i2 = si[tid+s];
            if (v2 > sv[tid] || (v2 == sv[tid] && i2 < si[tid])) { sv[tid] = v2; si[tid] = i2; }
        }
        __syncthreads();
    }
    const int amax = si[0];
    const int ci = (cur != nullptr) ? cur[0] : 0;
    for (int t = tid; t < Tx; t += 256) {
        long long p = (row[t] != 0) ? (long long)(t - amax) : (long long)1073741824;
        pos[b*Tx + t] = (float)(p + ci);
    }
}

// ---------------- RMSNorm + RoPE -------------------------------------------
__global__ __launch_bounds__(128)
void normrope_kernel(float* __restrict__ data, const float* __restrict__ scale,
                     const float* __restrict__ pos, int stride)
{
    const int token = blockIdx.x;
    const int h = blockIdx.y;
    const int tid = threadIdx.x;        // 0..127  -> pair (tid, tid+128)
    float* p = data + (size_t)token*stride + h*Dx;
    float a = p[tid];
    float b = p[tid + 128];
    // sum of squares over 256 elems
    float v2 = a*a + b*b;
    #pragma unroll
    for (int m = 16; m > 0; m >>= 1) v2 += __shfl_xor_sync(0xffffffffu, v2, m);
    __shared__ float red[4];
    if ((tid & 31) == 0) red[tid >> 5] = v2;
    __syncthreads();
    float total = red[0] + red[1] + red[2] + red[3];
    float inv = rsqrtf(total * (1.0f/256.0f) + 1e-6f);
    float an = a * inv * (1.0f + scale[tid]);
    float bn = b * inv * (1.0f + scale[tid + 128]);
    // rope
    float posv = pos[token];
    float frac = (float)tid * (1.0f/128.0f);            // 2*tid/256
    float freq = exp2f(-frac * 13.287712379549449f);    // 10000^-frac
    float ang = posv * freq;
    float s, c;
    sincosf(ang, &s, &c);
    p[tid]       = an*c - bn*s;
    p[tid + 128] = bn*c + an*s;
}

// ---------------- SGEMM 128x128x8, f32 -------------------------------------
__global__ __launch_bounds__(256)
void sgemm128(const float* __restrict__ A, const float* __restrict__ B,
              float* __restrict__ C, int M, int N, int K)
{
    __shared__ float As[8][128];
    __shared__ float Bs[8][128];
    const int tid = threadIdx.x;
    const int bx = blockIdx.x, by = blockIdx.y;
    const int tx = tid & 15, ty = tid >> 4;

    const int arow = tid >> 1;
    const int acol = (tid & 1) * 4;
    const float* Ag = A + (size_t)(by*128 + arow)*K + acol;
    const int brow = tid >> 5;
    const int bcol = (tid & 31) * 4;
    const float* Bg = B + (size_t)brow*N + bx*128 + bcol;

    float acc[8][8];
    #pragma unroll
    for (int i = 0; i < 8; i++)
        #pragma unroll
        for (int j = 0; j < 8; j++) acc[i][j] = 0.f;

    for (int k0 = 0; k0 < K; k0 += 8) {
        float4 av = *(const float4*)(Ag + k0);
        float4 bv = *(const float4*)(Bg + (size_t)k0*N);
        As[acol+0][arow] = av.x;
        As[acol+1][arow] = av.y;
        As[acol+2][arow] = av.z;
        As[acol+3][arow] = av.w;
        *(float4*)&Bs[brow][bcol] = bv;
        __syncthreads();
        #pragma unroll
        for (int kk = 0; kk < 8; kk++) {
            float4 a0 = *(float4*)&As[kk][ty*4];
            float4 a1 = *(float4*)&As[kk][64 + ty*4];
            float4 b0 = *(float4*)&Bs[kk][tx*4];
            float4 b1 = *(float4*)&Bs[kk][64 + tx*4];
            float a[8] = {a0.x,a0.y,a0.z,a0.w,a1.x,a1.y,a1.z,a1.w};
            float b[8] = {b0.x,b0.y,b0.z,b0.w,b1.x,b1.y,b1.z,b1.w};
            #pragma unroll
            for (int i = 0; i < 8; i++)
                #pragma unroll
                for (int j = 0; j < 8; j++)
                    acc[i][j] += a[i]*b[j];
        }
        __syncthreads();
    }
    #pragma unroll
    for (int i = 0; i < 8; i++) {
        int r = by*128 + ((i < 4) ? (ty*4 + i) : (64 + ty*4 + i - 4));
        float* Cr = C + (size_t)r*N + bx*128;
        *(float4*)(Cr + tx*4)      = make_float4(acc[i][0], acc[i][1], acc[i][2], acc[i][3]);
        *(float4*)(Cr + 64 + tx*4) = make_float4(acc[i][4], acc[i][5], acc[i][6], acc[i][7]);
    }
}

// ---------------- sliding-window flash attention ----------------------------
#define QS 260   /* smem row stride for Q/KV tiles */
#define PS 65    /* smem row stride for P tile */

extern __shared__ float att_smem[];

__global__ __launch_bounds__(256)
void attn_kernel(const float* __restrict__ Q, const float* __restrict__ Kc,
                 const float* __restrict__ Vc, float* __restrict__ O)
{
    float* sQ  = att_smem;              // 64*QS
    float* sKV = sQ  + 64*QS;           // 64*QS
    float* sP  = sKV + 64*QS;           // 64*PS
    float* sM  = sP  + 64*PS;           // 64
    float* sL  = sM  + 64;
    float* sAl = sL  + 64;
    float* sMn = sAl + 64;

    const int tid = threadIdx.x;
    const int qt = blockIdx.x, h = blockIdx.y, b = blockIdx.z;
    const int q0 = qt * 64;
    const int kvh = h >> 1;
    const float* Qb = Q  + (size_t)(b*Tx)*QSTR + h*Dx;
    const float* Kb = Kc + (size_t)(b*Tx)*KSTR + kvh*Dx;
    const float* Vb = Vc + (size_t)(b*Tx)*KSTR + kvh*Dx;

    // load Q tile (64 x 256)
    #pragma unroll
    for (int i = 0; i < 16; i++) {
        int f4  = tid + i*256;
        int row = f4 >> 6;
        int c4  = f4 & 63;
        float4 v = *(const float4*)(Qb + (size_t)(q0+row)*QSTR + c4*4);
        *(float4*)&sQ[row*QS + c4*4] = v;
    }
    if (tid < 64) { sM[tid] = -1e30f; sL[tid] = 0.f; }

    const int tq = tid >> 4;     // 0..15 (q group of 4)
    const int tk = tid & 15;     // 0..15 (k lanes; k = tk + 16*j)

    float4 o[4][4];              // [qi][dc] : q = tq*4+qi, d = tk*4 + 64*dc
    #pragma unroll
    for (int i = 0; i < 4; i++)
        #pragma unroll
        for (int c = 0; c < 4; c++) o[i][c] = make_float4(0.f,0.f,0.f,0.f);

    const int kt0 = (qt - 16 > 0) ? (qt - 16) : 0;
    for (int kt = kt0; kt <= qt; kt++) {
        __syncthreads();                    // prev PV done / Q load done
        // load K tile into sKV
        #pragma unroll
        for (int i = 0; i < 16; i++) {
            int f4  = tid + i*256;
            int row = f4 >> 6;
            int c4  = f4 & 63;
            float4 v = *(const float4*)(Kb + (size_t)(kt*64+row)*KSTR + c4*4);
            *(float4*)&sKV[row*QS + c4*4] = v;
        }
        __syncthreads();

        // ---- S = Q K^T  (each thread: 4q x 4k) ----
        float s[4][4];
        #pragma unroll
        for (int i = 0; i < 4; i++)
            #pragma unroll
            for (int j = 0; j < 4; j++) s[i][j] = 0.f;

        #pragma unroll 8
        for (int d4 = 0; d4 < 64; d4++) {
            float4 qv[4], kv[4];
            #pragma unroll
            for (int i = 0; i < 4; i++) qv[i] = *(float4*)&sQ[(tq*4+i)*QS + d4*4];
            #pragma unroll
            for (int j = 0; j < 4; j++) kv[j] = *(float4*)&sKV[(tk+16*j)*QS + d4*4];
            #pragma unroll
            for (int i = 0; i < 4; i++)
                #pragma unroll
                for (int j = 0; j < 4; j++)
                    s[i][j] += qv[i].x*kv[j].x + qv[i].y*kv[j].y
                             + qv[i].z*kv[j].z + qv[i].w*kv[j].w;
        }
        // mask + scale
        #pragma unroll
        for (int i = 0; i < 4; i++) {
            int qg = q0 + tq*4 + i;
            #pragma unroll
            for (int j = 0; j < 4; j++) {
                int kg = kt*64 + tk + 16*j;
                bool ok = (kg <= qg) && (qg - kg < WINDOWx);
                s[i][j] = ok ? s[i][j] * 0.0625f : -1e30f;
            }
        }
        // online softmax (reduce over 16 tk lanes)
        #pragma unroll
        for (int i = 0; i < 4; i++) {
            int q = tq*4 + i;
            float rm = fmaxf(fmaxf(s[i][0], s[i][1]), fmaxf(s[i][2], s[i][3]));
            #pragma unroll
            for (int m = 1; m < 16; m <<= 1) rm = fmaxf(rm, __shfl_xor_sync(0xffffffffu, rm, m));
            float mo = sM[q];
            float mn = fmaxf(mo, rm);
            float rs = 0.f;
            #pragma unroll
            for (int j = 0; j < 4; j++) {
                float pv = (s[i][j] > -1e29f) ? __expf(s[i][j] - mn) : 0.f;
                sP[q*PS + tk + 16*j] = pv;
                rs += pv;
            }
            #pragma unroll
            for (int m = 1; m < 16; m <<= 1) rs += __shfl_xor_sync(0xffffffffu, rs, m);
            if (tk == 0) {
                float al = __expf(mo - mn);
                sAl[q] = al;
                sL[q]  = sL[q]*al + rs;
                sMn[q] = mn;
            }
        }
        __syncthreads();

        // load V tile into sKV (K no longer needed); carry sM <- sMn
        #pragma unroll
        for (int i = 0; i < 16; i++) {
            int f4  = tid + i*256;
            int row = f4 >> 6;
            int c4  = f4 & 63;
            float4 v = *(const float4*)(Vb + (size_t)(kt*64+row)*KSTR + c4*4);
            *(float4*)&sKV[row*QS + c4*4] = v;
        }
        if (tid < 64) sM[tid] = sMn[tid];
        __syncthreads();

        // ---- O = alpha*O + P V ----
        #pragma unroll
        for (int i = 0; i < 4; i++) {
            float al = sAl[tq*4 + i];
            #pragma unroll
            for (int c = 0; c < 4; c++) {
                o[i][c].x *= al; o[i][c].y *= al; o[i][c].z *= al; o[i][c].w *= al;
            }
        }
        #pragma unroll 4
        for (int k = 0; k < 64; k++) {
            float4 vv[4];
            #pragma unroll
            for (int c = 0; c < 4; c++) vv[c] = *(float4*)&sKV[k*QS + tk*4 + 64*c];
            float pj[4];
            #pragma unroll
            for (int i = 0; i < 4; i++) pj[i] = sP[(tq*4+i)*PS + k];
            #pragma unroll
            for (int i = 0; i < 4; i++)
                #pragma unroll
                for (int c = 0; c < 4; c++) {
                    o[i][c].x += pj[i]*vv[c].x;
                    o[i][c].y += pj[i]*vv[c].y;
                    o[i][c].z += pj[i]*vv[c].z;
                    o[i][c].w += pj[i]*vv[c].w;
                }
        }
    }

    // epilogue: normalize and write
    #pragma unroll
    for (int i = 0; i < 4; i++) {
        int q = tq*4 + i;
        float inv = 1.0f / sL[q];
        float* Ob = O + (size_t)(b*Tx + q0 + q)*QSTR + h*Dx;
        #pragma unroll
        for (int c = 0; c < 4; c++) {
            float4 w = o[i][c];
            w.x *= inv; w.y *= inv; w.z *= inv; w.w *= inv;
            *(float4*)(Ob + tk*4 + 64*c) = w;
        }
    }
}

// ---------------- launch -----------------------------------------------------
extern "C" void kernel_launch(void* const* d_in, const int* in_sizes, int n_in,
                              void* d_out, int out_size)
{
    const float* x  = (const float*)d_in[0];
    const float* Wq = (const float*)d_in[1];
    const float* Wk = (const float*)d_in[2];
    const float* Wv = (const float*)d_in[3];
    const float* Wo = (const float*)d_in[4];
    const float* qs = (const float*)d_in[5];
    const float* ks = (const float*)d_in[6];
    const int*  seg = (const int*)d_in[7];
    const int*  cur = (n_in > 9) ? (const int*)d_in[9] : nullptr;
    float* out = (float*)d_out;
    (void)in_sizes; (void)out_size;

    float *q, *k, *v, *att, *pos;
    cudaGetSymbolAddress((void**)&q,   g_q);
    cudaGetSymbolAddress((void**)&k,   g_k);
    cudaGetSymbolAddress((void**)&v,   g_v);
    cudaGetSymbolAddress((void**)&att, g_att);
    cudaGetSymbolAddress((void**)&pos, g_pos);

    pos_kernel<<<Bx, 256>>>(seg, cur, pos);

    sgemm128<<<dim3(QSTR/128, NTOK/128), 256>>>(x, Wq, q, NTOK, QSTR, Hx);
    sgemm128<<<dim3(KSTR/128, NTOK/128), 256>>>(x, Wk, k, NTOK, KSTR, Hx);
    sgemm128<<<dim3(KSTR/128, NTOK/128), 256>>>(x, Wv, v, NTOK, KSTR, Hx);

    normrope_kernel<<<dim3(NTOK, NHx),  128>>>(q, qs, pos, QSTR);
    normrope_kernel<<<dim3(NTOK, NKVx), 128>>>(k, ks, pos, KSTR);

    size_t shm = (size_t)(64*QS*2 + 64*PS + 4*64) * sizeof(float);
    cudaFuncSetAttribute(attn_kernel, cudaFuncAttributeMaxDynamicSharedMemorySize, (int)shm);
    attn_kernel<<<dim3(Tx/64, NHx, Bx), 256, shm>>>(q, k, v, att);

    sgemm128<<<dim3(Hx/128, NTOK/128), 256>>>(att, Wo, out, NTOK, Hx, QSTR);
}

// round 3
// speedup vs baseline: 3.2395x; 3.2395x over previous
#include <cuda_runtime.h>
#include <math.h>
#include <stdint.h>

#define Bx 2
#define Tx 2048
#define Hx 2560
#define NHx 8
#define NKVx 4
#define Dx 256
#define WINDOWx 1024
#define NTOK (Bx*Tx)      /* 4096 */
#define QSTR (NHx*Dx)     /* 2048 */
#define KSTR (NKVx*Dx)    /* 1024 */

// ---------------- scratch (device globals; no allocation allowed) -----------
__device__ float g_q[NTOK*QSTR];
__device__ float g_k[NTOK*KSTR];
__device__ float g_v[NTOK*KSTR];
__device__ float g_att[NTOK*QSTR];
__device__ float g_pos[NTOK];
// tf32-rounded copies of inputs
__device__ float g_xr[NTOK*Hx];
__device__ float g_wqr[Hx*QSTR];
__device__ float g_wkr[Hx*KSTR];
__device__ float g_wvr[Hx*KSTR];
__device__ float g_wor[QSTR*Hx];

// ---------------- helpers ---------------------------------------------------
__device__ __forceinline__ uint32_t f2b(float x){ return __float_as_uint(x); }
__device__ __forceinline__ float tf32r(float x){
    uint32_t u; asm("cvt.rna.tf32.f32 %0, %1;" : "=r"(u) : "f"(x));
    return __uint_as_float(u);
}
__device__ __forceinline__ void mma8(float c[4], uint32_t a0, uint32_t a1,
                                     uint32_t a2, uint32_t a3,
                                     uint32_t b0, uint32_t b1){
    asm volatile("mma.sync.aligned.m16n8k8.row.col.f32.tf32.tf32.f32 "
                 "{%0,%1,%2,%3},{%4,%5,%6,%7},{%8,%9},{%0,%1,%2,%3};"
                 : "+f"(c[0]),"+f"(c[1]),"+f"(c[2]),"+f"(c[3])
                 : "r"(a0),"r"(a1),"r"(a2),"r"(a3),"r"(b0),"r"(b1));
}
__device__ __forceinline__ void cpa16(uint32_t dst, const float* src){
    asm volatile("cp.async.cg.shared.global [%0], [%1], 16;\n" :: "r"(dst), "l"(src));
}
#define CP_COMMIT() asm volatile("cp.async.commit_group;\n")
#define CP_WAIT0()  asm volatile("cp.async.wait_group 0;\n")
#define CP_WAIT1()  asm volatile("cp.async.wait_group 1;\n")
__device__ __forceinline__ uint32_t cvta_s(const void* p){
    return (uint32_t)__cvta_generic_to_shared(p);
}

// ---------------- tf32 rounding copy ----------------------------------------
__global__ void round_copy(const float* __restrict__ src, float* __restrict__ dst, int n){
    int i = blockIdx.x*blockDim.x + threadIdx.x;
    if (i < n) dst[i] = tf32r(src[i]);
}

// ---------------- position kernel ------------------------------------------
__global__ void pos_kernel(const int* __restrict__ seg, const int* __restrict__ cur,
                           float* __restrict__ pos)
{
    const int b = blockIdx.x;
    const int tid = threadIdx.x;
    const int* row = seg + b*Tx;
    __shared__ int sv[256], si[256];
    int bestv = -2147483647, besti = 0;
    for (int t = tid; t < Tx; t += 256) {
        int v = row[t];
        if (v > bestv) { bestv = v; besti = t; }
    }
    sv[tid] = bestv; si[tid] = besti;
    __syncthreads();
    for (int s = 128; s > 0; s >>= 1) {
        if (tid < s) {
            int v2 = sv[tid+s], i2 = si[tid+s];
            if (v2 > sv[tid] || (v2 == sv[tid] && i2 < si[tid])) { sv[tid] = v2; si[tid] = i2; }
        }
        __syncthreads();
    }
    const int amax = si[0];
    const int ci = (cur != nullptr) ? cur[0] : 0;
    for (int t = tid; t < Tx; t += 256) {
        long long p = (row[t] != 0) ? (long long)(t - amax) : (long long)1073741824;
        pos[b*Tx + t] = (float)(p + ci);
    }
}

// ---------------- RMSNorm + RoPE (outputs rounded to tf32) ------------------
__global__ __launch_bounds__(128)
void normrope_kernel(float* __restrict__ data, const float* __restrict__ scale,
                     const float* __restrict__ pos, int stride)
{
    const int token = blockIdx.x;
    const int h = blockIdx.y;
    const int tid = threadIdx.x;
    float* p = data + (size_t)token*stride + h*Dx;
    float a = p[tid];
    float b = p[tid + 128];
    float v2 = a*a + b*b;
    #pragma unroll
    for (int m = 16; m > 0; m >>= 1) v2 += __shfl_xor_sync(0xffffffffu, v2, m);
    __shared__ float red[4];
    if ((tid & 31) == 0) red[tid >> 5] = v2;
    __syncthreads();
    float total = red[0] + red[1] + red[2] + red[3];
    float inv = rsqrtf(total * (1.0f/256.0f) + 1e-6f);
    float an = a * inv * (1.0f + scale[tid]);
    float bn = b * inv * (1.0f + scale[tid + 128]);
    float posv = pos[token];
    float frac = (float)tid * (1.0f/128.0f);
    float freq = exp2f(-frac * 13.287712379549449f);
    float ang = posv * freq;
    float s, c;
    sincosf(ang, &s, &c);
    p[tid]       = tf32r(an*c - bn*s);
    p[tid + 128] = tf32r(bn*c + an*s);
}

// ---------------- tf32 tensor-core GEMM 128x128x32 --------------------------
// A row-major MxK, B row-major KxN, C row-major. M,N % 128 == 0, K % 32 == 0.
#define GASTR 36
#define GBSTR 136
#define GEMM_SMEM ((2*128*GASTR + 2*32*GBSTR)*4)

__global__ __launch_bounds__(256)
void gemm_tf32(const float* __restrict__ A, const float* __restrict__ B,
               float* __restrict__ C, int M, int N, int K, int roundC)
{
    extern __shared__ float gsm[];
    float* As = gsm;
    float* Bs = gsm + 2*128*GASTR;
    const int tid = threadIdx.x;
    const int warp = tid >> 5, lane = tid & 31;
    const int wm = warp >> 2, wn = warp & 3;
    const int l4 = lane >> 2, lk = lane & 3;
    const size_t m_blk = (size_t)blockIdx.y * 128;
    const size_t n_blk = (size_t)blockIdx.x * 128;
    const float* Ag = A + m_blk * K;
    const float* Bg = B + n_blk;

    float c[4][4][4];
    #pragma unroll
    for (int i = 0; i < 4; i++)
        #pragma unroll
        for (int j = 0; j < 4; j++)
            #pragma unroll
            for (int r = 0; r < 4; r++) c[i][j][r] = 0.f;

    const int KT = K >> 5;

    auto load_stage = [&](int kt, int s){
        float* as = As + s*(128*GASTR);
        float* bs = Bs + s*(32*GBSTR);
        const int k0 = kt*32;
        #pragma unroll
        for (int i = 0; i < 4; i++){
            int r = (tid>>3) + i*32;
            cpa16(cvta_s(as + r*GASTR + (tid&7)*4), Ag + (size_t)r*K + k0 + (tid&7)*4);
        }
        #pragma unroll
        for (int i = 0; i < 4; i++){
            int r = (tid>>5) + i*8;
            cpa16(cvta_s(bs + r*GBSTR + (tid&31)*4), Bg + (size_t)(k0+r)*N + (tid&31)*4);
        }
        CP_COMMIT();
    };

    load_stage(0, 0);
    for (int kt = 0; kt < KT; kt++){
        const int s = kt & 1;
        if (kt + 1 < KT){ load_stage(kt+1, s^1); CP_WAIT1(); }
        else            { CP_WAIT0(); }
        __syncthreads();
        const float* as = As + s*(128*GASTR);
        const float* bs = Bs + s*(32*GBSTR);
        #pragma unroll
        for (int kk = 0; kk < 4; kk++){
            uint32_t af[4][4], bf[4][2];
            const int kb = kk*8;
            #pragma unroll
            for (int mt = 0; mt < 4; mt++){
                const float* ap = as + (wm*64 + mt*16 + l4)*GASTR + kb + lk;
                af[mt][0] = f2b(ap[0]);
                af[mt][1] = f2b(ap[8*GASTR]);
                af[mt][2] = f2b(ap[4]);
                af[mt][3] = f2b(ap[8*GASTR+4]);
            }
            #pragma unroll
            for (int nt = 0; nt < 4; nt++){
                const float* bp = bs + (kb + lk)*GBSTR + wn*32 + nt*8 + l4;
                bf[nt][0] = f2b(bp[0]);
                bf[nt][1] = f2b(bp[4*GBSTR]);
            }
            #pragma unroll
            for (int mt = 0; mt < 4; mt++)
                #pragma unroll
                for (int nt = 0; nt < 4; nt++)
                    mma8(c[mt][nt], af[mt][0],af[mt][1],af[mt][2],af[mt][3],
                         bf[nt][0], bf[nt][1]);
        }
        __syncthreads();
    }

    #pragma unroll
    for (int mt = 0; mt < 4; mt++){
        const size_t r0 = m_blk + wm*64 + mt*16 + l4;
        #pragma unroll
        for (int nt = 0; nt < 4; nt++){
            const size_t cc = n_blk + wn*32 + nt*8 + lk*2;
            float2 v0 = make_float2(c[mt][nt][0], c[mt][nt][1]);
            float2 v1 = make_float2(c[mt][nt][2], c[mt][nt][3]);
            if (roundC){
                v0.x = tf32r(v0.x); v0.y = tf32r(v0.y);
                v1.x = tf32r(v1.x); v1.y = tf32r(v1.y);
            }
            *(float2*)(C + r0*N + cc)     = v0;
            *(float2*)(C + (r0+8)*N + cc) = v1;
        }
    }
}

// ---------------- tf32 flash attention --------------------------------------
#define AQS 260   /* Q / K smem row stride */
#define AVS 264   /* V smem row stride */
#define APS 68    /* P smem row stride */
#define ATT_SMEM ((64*AQS + 64*AVS + 64*APS + 3*64)*4)

__global__ __launch_bounds__(256)
void attn_tf32(const float* __restrict__ Q, const float* __restrict__ Kc,
               const float* __restrict__ Vc, float* __restrict__ O)
{
    extern __shared__ float att_sm[];
    float* sQ  = att_sm;
    float* sKV = sQ  + 64*AQS;
    float* sP  = sKV + 64*AVS;
    float* sM  = sP  + 64*APS;
    float* sL  = sM  + 64;
    float* sAl = sL  + 64;

    const int tid = threadIdx.x, warp = tid >> 5, lane = tid & 31;
    const int l4 = lane >> 2, lk = lane & 3;
    const int qt = blockIdx.x, h = blockIdx.y, b = blockIdx.z;
    const int q0 = qt * 64, kvh = h >> 1;
    const float* Qb = Q  + (size_t)(b*Tx)*QSTR + h*Dx;
    const float* Kb = Kc + (size_t)(b*Tx)*KSTR + kvh*Dx;
    const float* Vb = Vc + (size_t)(b*Tx)*KSTR + kvh*Dx;

    // Q tile (64 x 256) via cp.async
    #pragma unroll
    for (int i = 0; i < 16; i++){
        int idx = tid + i*256;
        int r = idx >> 6, c4 = idx & 63;
        cpa16(cvta_s(sQ + r*AQS + c4*4), Qb + (size_t)(q0+r)*QSTR + c4*4);
    }
    CP_COMMIT();
    if (tid < 64){ sM[tid] = -1e30f; sL[tid] = 0.f; }

    const int wms = warp >> 1, wns = warp & 1;   // S grid: 4m x 2n (warp 16x32)
    const int wmp = warp >> 2, wnp = warp & 3;   // PV grid: 2m x 4n (warp 32x64)

    float o[2][8][4];
    #pragma unroll
    for (int i = 0; i < 2; i++)
        #pragma unroll
        for (int j = 0; j < 8; j++)
            #pragma unroll
            for (int r = 0; r < 4; r++) o[i][j][r] = 0.f;

    const int kt0 = (qt > 16) ? qt - 16 : 0;
    for (int kt = kt0; kt <= qt; kt++){
        __syncthreads();                         // prev PV done with sKV
        #pragma unroll
        for (int i = 0; i < 16; i++){
            int idx = tid + i*256;
            int r = idx >> 6, c4 = idx & 63;
            cpa16(cvta_s(sKV + r*AQS + c4*4), Kb + (size_t)(kt*64+r)*KSTR + c4*4);
        }
        CP_COMMIT();
        CP_WAIT0();
        __syncthreads();

        // ---- S = Q K^T (tf32 mma) ----
        float s[4][4];
        #pragma unroll
        for (int nt = 0; nt < 4; nt++)
            #pragma unroll
            for (int r = 0; r < 4; r++) s[nt][r] = 0.f;

        #pragma unroll 4
        for (int d8 = 0; d8 < 32; d8++){
            const float* ap = sQ + (wms*16 + l4)*AQS + d8*8 + lk;
            uint32_t a0 = f2b(ap[0]), a1 = f2b(ap[8*AQS]);
            uint32_t a2 = f2b(ap[4]), a3 = f2b(ap[8*AQS+4]);
            #pragma unroll
            for (int nt = 0; nt < 4; nt++){
                const float* bp = sKV + (wns*32 + nt*8 + l4)*AQS + d8*8 + lk;
                mma8(s[nt], a0, a1, a2, a3, f2b(bp[0]), f2b(bp[4]));
            }
        }

        // mask + scale, store logits to sP
        #pragma unroll
        for (int nt = 0; nt < 4; nt++){
            const int cbase = wns*32 + nt*8 + lk*2;
            const int kg0 = kt*64 + cbase;
            #pragma unroll
            for (int half = 0; half < 2; half++){
                const int r  = wms*16 + l4 + half*8;
                const int qg = q0 + r;
                float2 v;
                v.x = (kg0   <= qg && qg - kg0   < WINDOWx) ? s[nt][half*2+0]*0.0625f : -1e30f;
                v.y = (kg0+1 <= qg && qg - (kg0+1) < WINDOWx) ? s[nt][half*2+1]*0.0625f : -1e30f;
                *(float2*)(sP + r*APS + cbase) = v;
            }
        }
        __syncthreads();

        // V tile cp.async (overlaps with softmax below)
        #pragma unroll
        for (int i = 0; i < 16; i++){
            int idx = tid + i*256;
            int r = idx >> 6, c4 = idx & 63;
            cpa16(cvta_s(sKV + r*AVS + c4*4), Vb + (size_t)(kt*64+r)*KSTR + c4*4);
        }
        CP_COMMIT();

        // ---- online softmax: 4 threads per row, 16 cols each ----
        {
            const int row = tid >> 2;
            const int cg  = (tid & 3) * 16;
            float* pr = sP + row*APS + cg;
            float4 p0 = *(float4*)(pr + 0);
            float4 p1 = *(float4*)(pr + 4);
            float4 p2 = *(float4*)(pr + 8);
            float4 p3 = *(float4*)(pr + 12);
            float rm = fmaxf(fmaxf(fmaxf(p0.x,p0.y),fmaxf(p0.z,p0.w)),
                             fmaxf(fmaxf(fmaxf(p1.x,p1.y),fmaxf(p1.z,p1.w)),
                             fmaxf(fmaxf(fmaxf(p2.x,p2.y),fmaxf(p2.z,p2.w)),
                                   fmaxf(fmaxf(p3.x,p3.y),fmaxf(p3.z,p3.w)))));
            rm = fmaxf(rm, __shfl_xor_sync(0xffffffffu, rm, 1));
            rm = fmaxf(rm, __shfl_xor_sync(0xffffffffu, rm, 2));
            const float mo = sM[row];
            const float mn = fmaxf(mo, rm);
            float rs = 0.f;
            #define AEXP(t) { t = (t > -1e29f) ? __expf(t - mn) : 0.f; rs += t; t = tf32r(t); }
            AEXP(p0.x); AEXP(p0.y); AEXP(p0.z); AEXP(p0.w);
            AEXP(p1.x); AEXP(p1.y); AEXP(p1.z); AEXP(p1.w);
            AEXP(p2.x); AEXP(p2.y); AEXP(p2.z); AEXP(p2.w);
            AEXP(p3.x); AEXP(p3.y); AEXP(p3.z); AEXP(p3.w);
            #undef AEXP
            *(float4*)(pr + 0)  = p0;
            *(float4*)(pr + 4)  = p1;
            *(float4*)(pr + 8)  = p2;
            *(float4*)(pr + 12) = p3;
            rs += __shfl_xor_sync(0xffffffffu, rs, 1);
            rs += __shfl_xor_sync(0xffffffffu, rs, 2);
            if ((tid & 3) == 0){
                float al = __expf(mo - mn);
                sAl[row] = al;
                sL[row]  = sL[row]*al + rs;
                sM[row]  = mn;
            }
        }
        CP_WAIT0();
        __syncthreads();

        // ---- O = alpha*O + P V ----
        const float a00 = sAl[wmp*32 + l4];
        const float a01 = sAl[wmp*32 + l4 + 8];
        const float a10 = sAl[wmp*32 + 16 + l4];
        const float a11 = sAl[wmp*32 + 16 + l4 + 8];
        #pragma unroll
        for (int nt = 0; nt < 8; nt++){
            o[0][nt][0]*=a00; o[0][nt][1]*=a00; o[0][nt][2]*=a01; o[0][nt][3]*=a01;
            o[1][nt][0]*=a10; o[1][nt][1]*=a10; o[1][nt][2]*=a11; o[1][nt][3]*=a11;
        }
        #pragma unroll
        for (int k8 = 0; k8 < 8; k8++){
            uint32_t af[2][4];
            #pragma unroll
            for (int mt = 0; mt < 2; mt++){
                const float* ap = sP + (wmp*32 + mt*16 + l4)*APS + k8*8 + lk;
                af[mt][0] = f2b(ap[0]);
                af[mt][1] = f2b(ap[8*APS]);
                af[mt][2] = f2b(ap[4]);
                af[mt][3] = f2b(ap[8*APS+4]);
            }
            #pragma unroll
            for (int nt = 0; nt < 8; nt++){
                const float* bp = sKV + (k8*8 + lk)*AVS + wnp*64 + nt*8 + l4;
                uint32_t b0 = f2b(bp[0]), b1 = f2b(bp[4*AVS]);
                #pragma unroll
                for (int mt = 0; mt < 2; mt++)
                    mma8(o[mt][nt], af[mt][0],af[mt][1],af[mt][2],af[mt][3], b0, b1);
            }
        }
    }

    // epilogue: normalize, round to tf32 (feeds Wo GEMM), write
    #pragma unroll
    for (int mt = 0; mt < 2; mt++){
        const int r0 = wmp*32 + mt*16 + l4;
        const float i0 = 1.0f / sL[r0];
        const float i1 = 1.0f / sL[r0+8];
        float* Ob0 = O + (size_t)(b*Tx + q0 + r0)*QSTR + h*Dx;
        float* Ob1 = O + (size_t)(b*Tx + q0 + r0 + 8)*QSTR + h*Dx;
        #pragma unroll
        for (int nt = 0; nt < 8; nt++){
            const int cc = wnp*64 + nt*8 + lk*2;
            float2 v0 = make_float2(tf32r(o[mt][nt][0]*i0), tf32r(o[mt][nt][1]*i0));
            float2 v1 = make_float2(tf32r(o[mt][nt][2]*i1), tf32r(o[mt][nt][3]*i1));
            *(float2*)(Ob0 + cc) = v0;
            *(float2*)(Ob1 + cc) = v1;
        }
    }
}

// ---------------- launch -----------------------------------------------------
extern "C" void kernel_launch(void* const* d_in, const int* in_sizes, int n_in,
                              void* d_out, int out_size)
{
    const float* x  = (const float*)d_in[0];
    const float* Wq = (const float*)d_in[1];
    const float* Wk = (const float*)d_in[2];
    const float* Wv = (const float*)d_in[3];
    const float* Wo = (const float*)d_in[4];
    const float* qs = (const float*)d_in[5];
    const float* ks = (const float*)d_in[6];
    const int*  seg = (const int*)d_in[7];
    const int*  cur = (n_in > 9) ? (const int*)d_in[9] : nullptr;
    float* out = (float*)d_out;
    (void)in_sizes; (void)out_size;

    float *q, *k, *v, *att, *pos, *xr, *wqr, *wkr, *wvr, *wor;
    cudaGetSymbolAddress((void**)&q,   g_q);
    cudaGetSymbolAddress((void**)&k,   g_k);
    cudaGetSymbolAddress((void**)&v,   g_v);
    cudaGetSymbolAddress((void**)&att, g_att);
    cudaGetSymbolAddress((void**)&pos, g_pos);
    cudaGetSymbolAddress((void**)&xr,  g_xr);
    cudaGetSymbolAddress((void**)&wqr, g_wqr);
    cudaGetSymbolAddress((void**)&wkr, g_wkr);
    cudaGetSymbolAddress((void**)&wvr, g_wvr);
    cudaGetSymbolAddress((void**)&wor, g_wor);

    cudaFuncSetAttribute(gemm_tf32, cudaFuncAttributeMaxDynamicSharedMemorySize, GEMM_SMEM);
    cudaFuncSetAttribute(attn_tf32, cudaFuncAttributeMaxDynamicSharedMemorySize, ATT_SMEM);

    pos_kernel<<<Bx, 256>>>(seg, cur, pos);

    // round inputs to tf32 (RNA) once
    round_copy<<<(NTOK*Hx+255)/256, 256>>>(x,  xr,  NTOK*Hx);
    round_copy<<<(Hx*QSTR+255)/256, 256>>>(Wq, wqr, Hx*QSTR);
    round_copy<<<(Hx*KSTR+255)/256, 256>>>(Wk, wkr, Hx*KSTR);
    round_copy<<<(Hx*KSTR+255)/256, 256>>>(Wv, wvr, Hx*KSTR);
    round_copy<<<(QSTR*Hx+255)/256, 256>>>(Wo, wor, QSTR*Hx);

    gemm_tf32<<<dim3(QSTR/128, NTOK/128), 256, GEMM_SMEM>>>(xr, wqr, q, NTOK, QSTR, Hx, 0);
    gemm_tf32<<<dim3(KSTR/128, NTOK/128), 256, GEMM_SMEM>>>(xr, wkr, k, NTOK, KSTR, Hx, 0);
    gemm_tf32<<<dim3(KSTR/128, NTOK/128), 256, GEMM_SMEM>>>(xr, wvr, v, NTOK, KSTR, Hx, 1);

    normrope_kernel<<<dim3(NTOK, NHx),  128>>>(q, qs, pos, QSTR);
    normrope_kernel<<<dim3(NTOK, NKVx), 128>>>(k, ks, pos, KSTR);

    attn_tf32<<<dim3(Tx/64, NHx, Bx), 256, ATT_SMEM>>>(q, k, v, att);

    gemm_tf32<<<dim3(Hx/128, NTOK/128), 256, GEMM_SMEM>>>(att, wor, out, NTOK, Hx, QSTR, 0);
}